// round 15
// baseline (speedup 1.0000x reference)
#include <cuda_runtime.h>
#include <cuda_fp16.h>
#include <math.h>
#include <stdint.h>

#define BATCH 8
#define REG   400
#define TLEN  1200
#define NB    5
#define NPSI  1024
#define LMAX  544
#define DMAX  576
#define NCMAX 6
#define MT    4
#define NT    19
#define XPAD  384
#define XE    2048
#define SBG   400   // global Bt row stride (halves)

#define SA_MAX     (NCMAX * 64 + 8)
#define SMEM_TOTAL ((128 + 64) * SA_MAX * 2)

static __device__ float  d_D[BATCH * NB][DMAX];
static __device__ int    d_L[BATCH * NB];
static __device__ int    d_OFF[BATCH * NB];
static __device__ int    d_NC[BATCH * NB];
static __device__ float  d_SQS[BATCH * NB];
static __device__ __align__(16) __half d_Xh[BATCH * REG][XE];
static __device__ __align__(16) __half d_Bt[BATCH * NB][64 * SBG];

__device__ __forceinline__ uint32_t smem_u32(const void* p) {
    uint32_t a;
    asm("{ .reg .u64 t; cvta.to.shared.u64 t, %1; cvt.u32.u64 %0, t; }"
        : "=r"(a) : "l"(p));
    return a;
}
#define LDSM4(r0, r1, r2, r3, a)                                             \
    asm volatile("ldmatrix.sync.aligned.m8n8.x4.shared.b16 {%0,%1,%2,%3}, [%4];" \
        : "=r"(r0), "=r"(r1), "=r"(r2), "=r"(r3) : "r"(a))
#define MMA(d, a, b)                                                         \
    asm volatile("mma.sync.aligned.m16n8k16.row.col.f32.f16.f16.f32 "        \
        "{%0,%1,%2,%3}, {%4,%5,%6,%7}, {%8,%9}, {%0,%1,%2,%3};"              \
        : "+f"((d)[0]), "+f"((d)[1]), "+f"((d)[2]), "+f"((d)[3])             \
        : "r"((a)[0]), "r"((a)[1]), "r"((a)[2]), "r"((a)[3]),                \
          "r"((b)[0]), "r"((b)[1]))

// ---------------- Kernel A: fp16 zero-extended signal ----------------
__global__ void k_conv(const float* __restrict__ ts) {
    const int r = blockIdx.x;
    const float* __restrict__ x = ts + (size_t)r * TLEN;
    __half* __restrict__ row = d_Xh[r];
    for (int t = threadIdx.x; t < XE; t += 256) {
        int u = t - XPAD;
        row[t] = __float2half_rn((u >= 0 && u < TLEN) ? x[u] : 0.0f);
    }
}

// ---------------- Kernel B: taps + truncation (OFF == 0 mod 8) ----------------
__global__ void k_prep(const float* __restrict__ tr, const float* __restrict__ lsp,
                       const float* __restrict__ bwp, float* __restrict__ out_bands) {
    __shared__ float sp[NPSI];
    __shared__ float shK[LMAX + 1];
    __shared__ float shDt[DMAX];
    __shared__ int s_lo, s_hi;

    const int bk = blockIdx.x, b = bk / NB, k = bk % NB, i = threadIdx.x;
    const float STEP_F = (float)(16.0 / 1023.0);

    for (int idx = i; idx < NPSI; idx += DMAX) {
        float x = -8.0f + STEP_F * (float)idx;
        sp[idx] = expf(-0.5f * x * x) * cosf(5.0f * x);
    }
    __syncthreads();
    for (int o = 1; o < NPSI; o <<= 1) {
        float a0 = 0.0f, a1 = 0.0f;
        int i1 = i + DMAX;
        if (i >= o) a0 = sp[i - o];
        if (i1 < NPSI && i1 >= o) a1 = sp[i1 - o];
        __syncthreads();
        sp[i] += a0;
        if (i1 < NPSI) sp[i1] += a1;
        __syncthreads();
    }

    const float trf   = tr[b] / 2.0f;
    const float scale = expf(lsp[k]) / trf;
    const float sstep = scale * STEP_F;
    const int   L0    = (int)floorf(scale * 16.0f) + 2;

    bool m = false;
    if (i < LMAX) {
        int j = (int)floorf((float)i / sstep);
        m = (i < L0) && (j < NPSI);
        int jc = min(max(j, 0), NPSI - 1);
        shK[i] = m ? sp[jc] * STEP_F : 0.0f;
    } else if (i == LMAX) shK[LMAX] = 0.0f;
    if (i == 0) { s_lo = DMAX; s_hi = -1; }
    const int L = __syncthreads_count(m);

    float dv = 0.0f;
    if (i <= L) dv = ((i == 0) ? 0.0f : shK[i - 1]) - shK[i];
    shDt[i] = dv;
    __syncthreads();

    const float thr = 1e-5f / scale;      // tight: error budget goes to fp16
    if (i < L && fabsf(shDt[i]) > thr) { atomicMin(&s_lo, i); atomicMax(&s_hi, i); }
    __syncthreads();

    const int base = (L - 2) / 2 + 1 - L;  // validated window origin (R7-R13)
    int lo, hi;
    if (s_hi >= s_lo) { lo = s_lo; hi = s_hi; } else { lo = 0; hi = L; }
    {   // force OFF = base + lo == 0 (mod 8); prefer extending left
        int s = (base + lo) & 7;
        if (s) { if (lo >= s) lo -= s; else lo += 8 - s; }
    }
    hi = min(hi, lo + 320);                // LD <= 321  =>  NC <= 6
    const int newLD = hi - lo + 1;

    d_D[bk][i] = (i < newLD) ? shDt[i + lo] : 0.0f;

    if (i == 0) {
        d_L[bk]   = newLD;
        d_OFF[bk] = base + lo;             // multiple of 8
        d_NC[bk]  = (newLD + 126) >> 6;    // ceil((LD+63)/64) <= 6
        d_SQS[bk] = sqrtf(scale);
        float center = 1.0f / (scale * tr[b]);
        float bw = bwp[k];
        out_bands[bk * 2 + 0] = fmaxf(0.008f, center * (1.0f - bw * 0.5f));
        out_bands[bk * 2 + 1] = fminf(0.12f,  center * (1.0f + bw * 0.5f));
    }
}

// ---------------- Kernel C: fp16 Toeplitz Bt[j][m] = D[m-j] ----------------
__global__ void k_bprep() {
    const int bk = blockIdx.x;
    const int L = d_L[bk], K = d_NC[bk] << 6;
    for (int e = threadIdx.x; e < 64 * K; e += 256) {
        int n = e / K, m2 = e - n * K;
        int di = m2 - n;
        float v = (di >= 0 && di < L) ? d_D[bk][di] : 0.0f;
        d_Bt[bk][n * SBG + m2] = __float2half_rn(v);
    }
}

// ---------------- Kernel D: Toeplitz GEMM via mma.sync (HMMA) ----------------
__global__ void __launch_bounds__(128, 1)
k_gemm(float* __restrict__ out) {
    extern __shared__ __align__(16) char smem[];
    const int tid = threadIdx.x, w = tid >> 5, lane = tid & 31;
    const int blk = blockIdx.x;
    const int bk = blk / (MT * NT), rem = blk % (MT * NT);
    const int mtile = rem / NT, ntile = rem % NT;
    const int b = bk / NB, band = bk % NB;
    const int n0 = ntile * 64;

    const int   OFF = d_OFF[bk];
    const int   NC  = d_NC[bk];
    const int   K   = NC << 6;
    const int   SA  = K + 8;               // halves; stride*2 == 16 mod 128
    const float sq  = d_SQS[bk];

    __half* sA = (__half*)smem;             // 128 x SA
    __half* sB = (__half*)smem + 128 * SA;  // 64  x SA

    // stage A: rows of fp16 signal
    const int KC = K >> 3;                  // 16B chunks per row
    const int xb = XPAD + n0 + OFF;         // multiple of 8
    for (int u = tid; u < 128 * KC; u += 128) {
        int r = u / KC, q = u - r * KC;
        int gl = mtile * 128 + r;
        uint4 v = make_uint4(0, 0, 0, 0);
        if (gl < REG)
            v = *(const uint4*)(&d_Xh[b * REG + gl][xb + q * 8]);
        *(uint4*)(&sA[r * SA + q * 8]) = v;
    }
    // stage Bt
    for (int u = tid; u < 64 * KC; u += 128) {
        int n = u / KC, q = u - n * KC;
        *(uint4*)(&sB[n * SA + q * 8]) = *(const uint4*)(&d_Bt[bk][n * SBG + q * 8]);
    }
    __syncthreads();

    // lane-fixed ldmatrix addresses
    const uint32_t sAb = smem_u32(sA), sBb = smem_u32(sB);
    const int rA = (lane & 7) + ((lane >> 3) & 1) * 8;
    const int cA = ((lane >> 4) & 1) * 8;
    uint32_t aAd0 = sAb + (uint32_t)(((w * 32 + rA) * SA + cA) << 1);
    uint32_t aAd1 = sAb + (uint32_t)(((w * 32 + 16 + rA) * SA + cA) << 1);
    const int rB = (lane & 7) + ((lane >> 4) & 1) * 8;
    const int cB = ((lane >> 3) & 1) * 8;
    uint32_t bAd0 = sBb + (uint32_t)(((rB)      * SA + cB) << 1);
    uint32_t bAd1 = sBb + (uint32_t)(((16 + rB) * SA + cB) << 1);
    uint32_t bAd2 = sBb + (uint32_t)(((32 + rB) * SA + cB) << 1);
    uint32_t bAd3 = sBb + (uint32_t)(((48 + rB) * SA + cB) << 1);

    float acc[2][8][4];
    #pragma unroll
    for (int s = 0; s < 2; s++)
        #pragma unroll
        for (int nt = 0; nt < 8; nt++)
            #pragma unroll
            for (int q = 0; q < 4; q++) acc[s][nt][q] = 0.0f;

    const int KS = NC << 2;                 // K/16 steps
    for (int ks = 0; ks < KS; ks++) {
        uint32_t a0[4], a1[4], bb[8][2];
        LDSM4(a0[0], a0[1], a0[2], a0[3], aAd0);
        LDSM4(a1[0], a1[1], a1[2], a1[3], aAd1);
        LDSM4(bb[0][0], bb[0][1], bb[1][0], bb[1][1], bAd0);
        LDSM4(bb[2][0], bb[2][1], bb[3][0], bb[3][1], bAd1);
        LDSM4(bb[4][0], bb[4][1], bb[5][0], bb[5][1], bAd2);
        LDSM4(bb[6][0], bb[6][1], bb[7][0], bb[7][1], bAd3);
        aAd0 += 32; aAd1 += 32;
        bAd0 += 32; bAd1 += 32; bAd2 += 32; bAd3 += 32;
        #pragma unroll
        for (int nt = 0; nt < 8; nt++) {
            MMA(acc[0][nt], a0, bb[nt]);
            MMA(acc[1][nt], a1, bb[nt]);
        }
    }

    // epilogue: scale * abs, direct paired stores (32B runs per 4-lane group)
    const int qn = lane & 3, rr = lane >> 2;
    #pragma unroll
    for (int s = 0; s < 2; s++) {
        #pragma unroll
        for (int h = 0; h < 2; h++) {
            int row = w * 32 + s * 16 + rr + h * 8;
            int gl  = mtile * 128 + row;
            if (gl < REG) {
                float* __restrict__ orow =
                    out + ((size_t)(b * REG + gl) * NB + band) * TLEN;
                #pragma unroll
                for (int nt = 0; nt < 8; nt++) {
                    int n = n0 + nt * 8 + qn * 2;
                    if (n < TLEN) {
                        float2 v;
                        v.x = sq * fabsf(acc[s][nt][h * 2 + 0]);
                        v.y = sq * fabsf(acc[s][nt][h * 2 + 1]);
                        *(float2*)(orow + n) = v;
                    }
                }
            }
        }
    }
}

// ---------------------------------------------------------------------------
extern "C" void kernel_launch(void* const* d_in, const int* in_sizes, int n_in,
                              void* d_out, int out_size) {
    (void)in_sizes; (void)n_in; (void)out_size;
    const float* ts  = (const float*)d_in[0];
    const float* tr  = (const float*)d_in[1];
    const float* lsp = (const float*)d_in[2];
    const float* bwp = (const float*)d_in[3];
    float* out   = (float*)d_out;
    float* bands = out + (size_t)BATCH * REG * NB * TLEN;

    cudaFuncSetAttribute(k_gemm, cudaFuncAttributeMaxDynamicSharedMemorySize,
                         SMEM_TOTAL);

    k_conv<<<BATCH * REG, 256>>>(ts);
    k_prep<<<BATCH * NB, DMAX>>>(tr, lsp, bwp, bands);
    k_bprep<<<BATCH * NB, 256>>>();
    k_gemm<<<BATCH * NB * MT * NT, 128, SMEM_TOTAL>>>(out);
}

// round 16
// speedup vs baseline: 1.7353x; 1.7353x over previous
#include <cuda_runtime.h>
#include <cuda_fp16.h>
#include <math.h>
#include <stdint.h>

#define BATCH 8
#define REG   400
#define TLEN  1200
#define NB    5
#define NPSI  1024
#define LMAX  544
#define DMAX  576
#define NCMAX 6
#define MT    4
#define NT    19
#define XPAD  384
#define XE    2048
#define SBG   400   // global Bt row stride (halves)

#define SA    72                       // chunk row stride (halves): 64 + 8
#define SMEM_TOTAL ((128 + 64) * SA * 2)   // 27648 B

static __device__ float  d_D[BATCH * NB][DMAX];
static __device__ int    d_L[BATCH * NB];
static __device__ int    d_OFF[BATCH * NB];
static __device__ int    d_NC[BATCH * NB];
static __device__ float  d_SQS[BATCH * NB];
static __device__ __align__(16) __half d_Xh[BATCH * REG][XE];
static __device__ __align__(16) __half d_Bt[BATCH * NB][64 * SBG];

__device__ __forceinline__ uint32_t smem_u32(const void* p) {
    uint32_t a;
    asm("{ .reg .u64 t; cvta.to.shared.u64 t, %1; cvt.u32.u64 %0, t; }"
        : "=r"(a) : "l"(p));
    return a;
}
#define LDSM4(r0, r1, r2, r3, a)                                             \
    asm volatile("ldmatrix.sync.aligned.m8n8.x4.shared.b16 {%0,%1,%2,%3}, [%4];" \
        : "=r"(r0), "=r"(r1), "=r"(r2), "=r"(r3) : "r"(a))
#define MMA(d, a, b)                                                         \
    asm volatile("mma.sync.aligned.m16n8k16.row.col.f32.f16.f16.f32 "        \
        "{%0,%1,%2,%3}, {%4,%5,%6,%7}, {%8,%9}, {%0,%1,%2,%3};"              \
        : "+f"((d)[0]), "+f"((d)[1]), "+f"((d)[2]), "+f"((d)[3])             \
        : "r"((a)[0]), "r"((a)[1]), "r"((a)[2]), "r"((a)[3]),                \
          "r"((b)[0]), "r"((b)[1]))

// ---------------- Kernel A: fp16 zero-extended signal ----------------
__global__ void k_conv(const float* __restrict__ ts) {
    const int r = blockIdx.x;
    const float* __restrict__ x = ts + (size_t)r * TLEN;
    __half* __restrict__ row = d_Xh[r];
    for (int t = threadIdx.x; t < XE; t += 256) {
        int u = t - XPAD;
        row[t] = __float2half_rn((u >= 0 && u < TLEN) ? x[u] : 0.0f);
    }
}

// ---------------- Kernel B: taps + truncation (OFF == 0 mod 8) ----------------
__global__ void k_prep(const float* __restrict__ tr, const float* __restrict__ lsp,
                       const float* __restrict__ bwp, float* __restrict__ out_bands) {
    __shared__ float sp[NPSI];
    __shared__ float shK[LMAX + 1];
    __shared__ float shDt[DMAX];
    __shared__ int s_lo, s_hi;

    const int bk = blockIdx.x, b = bk / NB, k = bk % NB, i = threadIdx.x;
    const float STEP_F = (float)(16.0 / 1023.0);

    for (int idx = i; idx < NPSI; idx += DMAX) {
        float x = -8.0f + STEP_F * (float)idx;
        sp[idx] = expf(-0.5f * x * x) * cosf(5.0f * x);
    }
    __syncthreads();
    for (int o = 1; o < NPSI; o <<= 1) {
        float a0 = 0.0f, a1 = 0.0f;
        int i1 = i + DMAX;
        if (i >= o) a0 = sp[i - o];
        if (i1 < NPSI && i1 >= o) a1 = sp[i1 - o];
        __syncthreads();
        sp[i] += a0;
        if (i1 < NPSI) sp[i1] += a1;
        __syncthreads();
    }

    const float trf   = tr[b] / 2.0f;
    const float scale = expf(lsp[k]) / trf;
    const float sstep = scale * STEP_F;
    const int   L0    = (int)floorf(scale * 16.0f) + 2;

    bool m = false;
    if (i < LMAX) {
        int j = (int)floorf((float)i / sstep);
        m = (i < L0) && (j < NPSI);
        int jc = min(max(j, 0), NPSI - 1);
        shK[i] = m ? sp[jc] * STEP_F : 0.0f;
    } else if (i == LMAX) shK[LMAX] = 0.0f;
    if (i == 0) { s_lo = DMAX; s_hi = -1; }
    const int L = __syncthreads_count(m);

    float dv = 0.0f;
    if (i <= L) dv = ((i == 0) ? 0.0f : shK[i - 1]) - shK[i];
    shDt[i] = dv;
    __syncthreads();

    const float thr = 1e-5f / scale;
    if (i < L && fabsf(shDt[i]) > thr) { atomicMin(&s_lo, i); atomicMax(&s_hi, i); }
    __syncthreads();

    const int base = (L - 2) / 2 + 1 - L;
    int lo, hi;
    if (s_hi >= s_lo) { lo = s_lo; hi = s_hi; } else { lo = 0; hi = L; }
    {   // force OFF = base + lo == 0 (mod 8)
        int s = (base + lo) & 7;
        if (s) { if (lo >= s) lo -= s; else lo += 8 - s; }
    }
    hi = min(hi, lo + 320);
    const int newLD = hi - lo + 1;

    d_D[bk][i] = (i < newLD) ? shDt[i + lo] : 0.0f;

    if (i == 0) {
        d_L[bk]   = newLD;
        d_OFF[bk] = base + lo;
        d_NC[bk]  = (newLD + 126) >> 6;
        d_SQS[bk] = sqrtf(scale);
        float center = 1.0f / (scale * tr[b]);
        float bw = bwp[k];
        out_bands[bk * 2 + 0] = fmaxf(0.008f, center * (1.0f - bw * 0.5f));
        out_bands[bk * 2 + 1] = fminf(0.12f,  center * (1.0f + bw * 0.5f));
    }
}

// ---------------- Kernel C: fp16 Toeplitz Bt[j][m] = D[m-j] ----------------
__global__ void k_bprep() {
    const int bk = blockIdx.x;
    const int L = d_L[bk], K = d_NC[bk] << 6;
    for (int e = threadIdx.x; e < 64 * K; e += 256) {
        int n = e / K, m2 = e - n * K;
        int di = m2 - n;
        float v = (di >= 0 && di < L) ? d_D[bk][di] : 0.0f;
        d_Bt[bk][n * SBG + m2] = __float2half_rn(v);
    }
}

// ---------------- Kernel D: Toeplitz GEMM via mma.sync, K-chunked ----------------
__global__ void __launch_bounds__(128, 4)
k_gemm(float* __restrict__ out) {
    extern __shared__ __align__(16) char smem[];
    const int tid = threadIdx.x, w = tid >> 5, lane = tid & 31;
    const int blk = blockIdx.x;
    const int bk = blk / (MT * NT), rem = blk % (MT * NT);
    const int mtile = rem / NT, ntile = rem % NT;
    const int b = bk / NB, band = bk % NB;
    const int n0 = ntile * 64;

    const int   OFF = d_OFF[bk];
    const int   NC  = d_NC[bk];
    const float sq  = d_SQS[bk];

    __half* sA = (__half*)smem;             // 128 x SA (one 64-K chunk)
    __half* sB = (__half*)smem + 128 * SA;  // 64  x SA

    const uint32_t sAb = smem_u32(sA), sBb = smem_u32(sB);
    // lane-fixed ldmatrix offsets (within a chunk)
    const int rA = (lane & 7) + ((lane >> 3) & 1) * 8;
    const int cA = ((lane >> 4) & 1) * 8;
    const uint32_t oA0 = (uint32_t)(((w * 32 + rA) * SA + cA) << 1);
    const uint32_t oA1 = (uint32_t)(((w * 32 + 16 + rA) * SA + cA) << 1);
    const int rB = (lane & 7) + ((lane >> 4) & 1) * 8;
    const int cB = ((lane >> 3) & 1) * 8;
    const uint32_t oB0 = (uint32_t)(((rB)      * SA + cB) << 1);
    const uint32_t oB1 = (uint32_t)(((16 + rB) * SA + cB) << 1);
    const uint32_t oB2 = (uint32_t)(((32 + rB) * SA + cB) << 1);
    const uint32_t oB3 = (uint32_t)(((48 + rB) * SA + cB) << 1);

    float acc[2][8][4];
    #pragma unroll
    for (int s = 0; s < 2; s++)
        #pragma unroll
        for (int nt = 0; nt < 8; nt++)
            #pragma unroll
            for (int q = 0; q < 4; q++) acc[s][nt][q] = 0.0f;

    const int glBase = b * REG + mtile * 128;

    for (int c = 0; c < NC; c++) {
        // ---- stage one 64-wide K chunk (A: 128 rows, B: 64 rows) ----
        const int xb = XPAD + n0 + OFF + c * 64;   // multiple of 8
        for (int u = tid; u < 128 * 8; u += 128) { // 8 x 16B per row
            int r = u >> 3, q = u & 7;
            int gl = glBase + r;
            uint4 v = make_uint4(0, 0, 0, 0);
            if (gl < b * REG + REG)
                v = *(const uint4*)(&d_Xh[gl][xb + q * 8]);
            *(uint4*)(&sA[r * SA + q * 8]) = v;
        }
        for (int u = tid; u < 64 * 8; u += 128) {
            int n = u >> 3, q = u & 7;
            *(uint4*)(&sB[n * SA + q * 8]) =
                *(const uint4*)(&d_Bt[bk][n * SBG + c * 64 + q * 8]);
        }
        __syncthreads();

        // ---- 4 K=16 steps over this chunk ----
        uint32_t aAd0 = sAb + oA0, aAd1 = sAb + oA1;
        uint32_t bAd0 = sBb + oB0, bAd1 = sBb + oB1;
        uint32_t bAd2 = sBb + oB2, bAd3 = sBb + oB3;
        #pragma unroll
        for (int ks = 0; ks < 4; ks++) {
            uint32_t a0[4], a1[4], bb[8][2];
            LDSM4(a0[0], a0[1], a0[2], a0[3], aAd0);
            LDSM4(a1[0], a1[1], a1[2], a1[3], aAd1);
            LDSM4(bb[0][0], bb[0][1], bb[1][0], bb[1][1], bAd0);
            LDSM4(bb[2][0], bb[2][1], bb[3][0], bb[3][1], bAd1);
            LDSM4(bb[4][0], bb[4][1], bb[5][0], bb[5][1], bAd2);
            LDSM4(bb[6][0], bb[6][1], bb[7][0], bb[7][1], bAd3);
            aAd0 += 32; aAd1 += 32;
            bAd0 += 32; bAd1 += 32; bAd2 += 32; bAd3 += 32;
            #pragma unroll
            for (int nt = 0; nt < 8; nt++) {
                MMA(acc[0][nt], a0, bb[nt]);
                MMA(acc[1][nt], a1, bb[nt]);
            }
        }
        __syncthreads();
    }

    // ---- epilogue: scale * abs, paired stores ----
    const int qn = lane & 3, rr = lane >> 2;
    #pragma unroll
    for (int s = 0; s < 2; s++) {
        #pragma unroll
        for (int h = 0; h < 2; h++) {
            int row = w * 32 + s * 16 + rr + h * 8;
            int gl  = mtile * 128 + row;
            if (gl < REG) {
                float* __restrict__ orow =
                    out + ((size_t)(b * REG + gl) * NB + band) * TLEN;
                #pragma unroll
                for (int nt = 0; nt < 8; nt++) {
                    int n = n0 + nt * 8 + qn * 2;
                    if (n < TLEN) {
                        float2 v;
                        v.x = sq * fabsf(acc[s][nt][h * 2 + 0]);
                        v.y = sq * fabsf(acc[s][nt][h * 2 + 1]);
                        *(float2*)(orow + n) = v;
                    }
                }
            }
        }
    }
}

// ---------------------------------------------------------------------------
extern "C" void kernel_launch(void* const* d_in, const int* in_sizes, int n_in,
                              void* d_out, int out_size) {
    (void)in_sizes; (void)n_in; (void)out_size;
    const float* ts  = (const float*)d_in[0];
    const float* tr  = (const float*)d_in[1];
    const float* lsp = (const float*)d_in[2];
    const float* bwp = (const float*)d_in[3];
    float* out   = (float*)d_out;
    float* bands = out + (size_t)BATCH * REG * NB * TLEN;

    cudaFuncSetAttribute(k_gemm, cudaFuncAttributeMaxDynamicSharedMemorySize,
                         SMEM_TOTAL);

    k_conv<<<BATCH * REG, 256>>>(ts);
    k_prep<<<BATCH * NB, DMAX>>>(tr, lsp, bwp, bands);
    k_bprep<<<BATCH * NB, 256>>>();
    k_gemm<<<BATCH * NB * MT * NT, 128, SMEM_TOTAL>>>(out);
}

// round 17
// speedup vs baseline: 2.0203x; 1.1642x over previous
#include <cuda_runtime.h>
#include <cuda_fp16.h>
#include <math.h>
#include <stdint.h>

#define BATCH 8
#define REG   400
#define TLEN  1200
#define NB    5
#define NPSI  1024
#define LMAX  544
#define DMAX  576
#define NCMAX 6
#define MT    4
#define NT    19
#define XPAD  384
#define XE    2048
#define SBG   400   // global Bt row stride (halves)

#define SA        72                        // chunk row stride (halves)
#define BUF_HALVES ((128 + 64) * SA)        // one pipeline stage
#define SMEM_TOTAL (2 * BUF_HALVES * 2)     // 55296 B

static __device__ int    d_L[BATCH * NB];
static __device__ int    d_OFF[BATCH * NB];
static __device__ int    d_NC[BATCH * NB];
static __device__ float  d_SQS[BATCH * NB];
static __device__ __align__(16) __half d_Xh[BATCH * REG][XE];
static __device__ __align__(16) __half d_Bt[BATCH * NB][64 * SBG];

__device__ __forceinline__ uint32_t smem_u32(const void* p) {
    uint32_t a;
    asm("{ .reg .u64 t; cvta.to.shared.u64 t, %1; cvt.u32.u64 %0, t; }"
        : "=r"(a) : "l"(p));
    return a;
}
#define LDSM4(r0, r1, r2, r3, a)                                             \
    asm volatile("ldmatrix.sync.aligned.m8n8.x4.shared.b16 {%0,%1,%2,%3}, [%4];" \
        : "=r"(r0), "=r"(r1), "=r"(r2), "=r"(r3) : "r"(a))
#define MMA(d, a, b)                                                         \
    asm volatile("mma.sync.aligned.m16n8k16.row.col.f32.f16.f16.f32 "        \
        "{%0,%1,%2,%3}, {%4,%5,%6,%7}, {%8,%9}, {%0,%1,%2,%3};"              \
        : "+f"((d)[0]), "+f"((d)[1]), "+f"((d)[2]), "+f"((d)[3])             \
        : "r"((a)[0]), "r"((a)[1]), "r"((a)[2]), "r"((a)[3]),                \
          "r"((b)[0]), "r"((b)[1]))
// cp.async 16B with zero-fill when sz==0 (OOB rows)
#define CPASYNC16(saddr, gptr, sz)                                           \
    asm volatile("cp.async.ca.shared.global [%0], [%1], 16, %2;"             \
        :: "r"(saddr), "l"(gptr), "r"(sz) : "memory")
#define CPCOMMIT() asm volatile("cp.async.commit_group;" ::: "memory")
#define CPWAIT(n)  asm volatile("cp.async.wait_group %0;" :: "n"(n) : "memory")

// ---------------- Kernel A: fp16 zero-extended signal ----------------
__global__ void k_conv(const float* __restrict__ ts) {
    const int r = blockIdx.x;
    const float* __restrict__ x = ts + (size_t)r * TLEN;
    __half* __restrict__ row = d_Xh[r];
    for (int t = threadIdx.x; t < XE; t += 256) {
        int u = t - XPAD;
        row[t] = __float2half_rn((u >= 0 && u < TLEN) ? x[u] : 0.0f);
    }
}

// ---------------- Kernel B: taps + truncation + Toeplitz Bt + bands ----------------
__global__ void k_prep(const float* __restrict__ tr, const float* __restrict__ lsp,
                       const float* __restrict__ bwp, float* __restrict__ out_bands) {
    __shared__ float sp[NPSI];
    __shared__ float shK[LMAX + 1];
    __shared__ float shDt[DMAX];
    __shared__ int s_lo, s_hi;

    const int bk = blockIdx.x, b = bk / NB, k = bk % NB, i = threadIdx.x;
    const float STEP_F = (float)(16.0 / 1023.0);

    for (int idx = i; idx < NPSI; idx += DMAX) {
        float x = -8.0f + STEP_F * (float)idx;
        sp[idx] = expf(-0.5f * x * x) * cosf(5.0f * x);
    }
    __syncthreads();
    for (int o = 1; o < NPSI; o <<= 1) {
        float a0 = 0.0f, a1 = 0.0f;
        int i1 = i + DMAX;
        if (i >= o) a0 = sp[i - o];
        if (i1 < NPSI && i1 >= o) a1 = sp[i1 - o];
        __syncthreads();
        sp[i] += a0;
        if (i1 < NPSI) sp[i1] += a1;
        __syncthreads();
    }

    const float trf   = tr[b] / 2.0f;
    const float scale = expf(lsp[k]) / trf;
    const float sstep = scale * STEP_F;
    const int   L0    = (int)floorf(scale * 16.0f) + 2;

    bool m = false;
    if (i < LMAX) {
        int j = (int)floorf((float)i / sstep);
        m = (i < L0) && (j < NPSI);
        int jc = min(max(j, 0), NPSI - 1);
        shK[i] = m ? sp[jc] * STEP_F : 0.0f;
    } else if (i == LMAX) shK[LMAX] = 0.0f;
    if (i == 0) { s_lo = DMAX; s_hi = -1; }
    const int L = __syncthreads_count(m);

    float dv = 0.0f;
    if (i <= L) dv = ((i == 0) ? 0.0f : shK[i - 1]) - shK[i];
    shDt[i] = dv;
    __syncthreads();

    const float thr = 1e-5f / scale;
    if (i < L && fabsf(shDt[i]) > thr) { atomicMin(&s_lo, i); atomicMax(&s_hi, i); }
    __syncthreads();

    const int base = (L - 2) / 2 + 1 - L;
    int lo, hi;
    if (s_hi >= s_lo) { lo = s_lo; hi = s_hi; } else { lo = 0; hi = L; }
    {   // force OFF = base + lo == 0 (mod 8)
        int s = (base + lo) & 7;
        if (s) { if (lo >= s) lo -= s; else lo += 8 - s; }
    }
    hi = min(hi, lo + 320);
    const int newLD = hi - lo + 1;
    const int NC = (newLD + 126) >> 6;
    const int K  = NC << 6;

    // fused Bt build straight from shDt: Bt[n][m] = D[m-n] = shDt[lo + m - n]
    for (int e = i; e < 64 * K; e += DMAX) {
        int n = e / K, m2 = e - n * K;
        int di = m2 - n;
        float v = (di >= 0 && di < newLD) ? shDt[lo + di] : 0.0f;
        d_Bt[bk][n * SBG + m2] = __float2half_rn(v);
    }

    if (i == 0) {
        d_L[bk]   = newLD;
        d_OFF[bk] = base + lo;
        d_NC[bk]  = NC;
        d_SQS[bk] = sqrtf(scale);
        float center = 1.0f / (scale * tr[b]);
        float bw = bwp[k];
        out_bands[bk * 2 + 0] = fmaxf(0.008f, center * (1.0f - bw * 0.5f));
        out_bands[bk * 2 + 1] = fminf(0.12f,  center * (1.0f + bw * 0.5f));
    }
}

// ---------------- Kernel C: Toeplitz GEMM, double-buffered cp.async ----------------
__global__ void __launch_bounds__(128, 4)
k_gemm(float* __restrict__ out) {
    extern __shared__ __align__(16) char smem[];
    const int tid = threadIdx.x, w = tid >> 5, lane = tid & 31;
    const int blk = blockIdx.x;
    const int bk = blk / (MT * NT), rem = blk % (MT * NT);
    const int mtile = rem / NT, ntile = rem % NT;
    const int b = bk / NB, band = bk % NB;
    const int n0 = ntile * 64;

    const int   OFF = d_OFF[bk];
    const int   NC  = d_NC[bk];
    const float sq  = d_SQS[bk];

    // per-thread staging coords (8 uint4 per 128-row A, 4 per 64-row B)
    const int arow = tid >> 3, aq = tid & 7;            // covers 16 rows/pass x8
    const uint32_t sbase = smem_u32(smem);

    // stage chunk c into buffer (c&1): A rows via 8 passes of 16 rows
    const int glA = b * REG + mtile * 128;
    const __half* btp = d_Bt[bk];

#define STAGE(c) do {                                                        \
        uint32_t bufo = (uint32_t)(((c) & 1) * BUF_HALVES * 2);              \
        int xb = XPAD + n0 + OFF + (c) * 64;                                 \
        for (int p = 0; p < 8; p++) {                                        \
            int r = p * 16 + arow;                                           \
            int gl = glA + r;                                                \
            uint32_t sz = (gl < (b + 1) * REG && gl < glA + 128) ? 16u : 0u; \
            (void)sz;                                                        \
            uint32_t sz2 = (mtile * 128 + r < REG) ? 16u : 0u;               \
            CPASYNC16(sbase + bufo + (uint32_t)((r * SA + aq * 8) << 1),     \
                      (const char*)&d_Xh[glA + r][xb + aq * 8], sz2);        \
        }                                                                    \
        for (int p = 0; p < 4; p++) {                                        \
            int n = p * 16 + arow;                                           \
            CPASYNC16(sbase + bufo + (uint32_t)((128 * SA + n * SA + aq * 8) << 1), \
                      (const char*)&btp[n * SBG + (c) * 64 + aq * 8], 16u);  \
        }                                                                    \
        CPCOMMIT();                                                          \
    } while (0)

    // lane-fixed ldmatrix offsets (within a buffer)
    const int rA = (lane & 7) + ((lane >> 3) & 1) * 8;
    const int cA = ((lane >> 4) & 1) * 8;
    const uint32_t oA0 = (uint32_t)(((w * 32 + rA) * SA + cA) << 1);
    const uint32_t oA1 = (uint32_t)(((w * 32 + 16 + rA) * SA + cA) << 1);
    const int rB = (lane & 7) + ((lane >> 4) & 1) * 8;
    const int cB = ((lane >> 3) & 1) * 8;
    const uint32_t oB0 = (uint32_t)(((128 + rB) * SA + cB) << 1);
    const uint32_t oB1 = (uint32_t)(((128 + 16 + rB) * SA + cB) << 1);
    const uint32_t oB2 = (uint32_t)(((128 + 32 + rB) * SA + cB) << 1);
    const uint32_t oB3 = (uint32_t)(((128 + 48 + rB) * SA + cB) << 1);

    float acc[2][8][4];
    #pragma unroll
    for (int s = 0; s < 2; s++)
        #pragma unroll
        for (int nt = 0; nt < 8; nt++)
            #pragma unroll
            for (int q = 0; q < 4; q++) acc[s][nt][q] = 0.0f;

    STAGE(0);

    for (int c = 0; c < NC; c++) {
        if (c + 1 < NC) {
            STAGE(c + 1);
            CPWAIT(1);                      // chunk c complete, c+1 in flight
        } else {
            CPWAIT(0);
        }
        __syncthreads();

        const uint32_t bufo = (uint32_t)((c & 1) * BUF_HALVES * 2);
        uint32_t aAd0 = sbase + bufo + oA0, aAd1 = sbase + bufo + oA1;
        uint32_t bAd0 = sbase + bufo + oB0, bAd1 = sbase + bufo + oB1;
        uint32_t bAd2 = sbase + bufo + oB2, bAd3 = sbase + bufo + oB3;
        #pragma unroll
        for (int ks = 0; ks < 4; ks++) {
            uint32_t a0[4], a1[4], bb[8][2];
            LDSM4(a0[0], a0[1], a0[2], a0[3], aAd0);
            LDSM4(a1[0], a1[1], a1[2], a1[3], aAd1);
            LDSM4(bb[0][0], bb[0][1], bb[1][0], bb[1][1], bAd0);
            LDSM4(bb[2][0], bb[2][1], bb[3][0], bb[3][1], bAd1);
            LDSM4(bb[4][0], bb[4][1], bb[5][0], bb[5][1], bAd2);
            LDSM4(bb[6][0], bb[6][1], bb[7][0], bb[7][1], bAd3);
            aAd0 += 32; aAd1 += 32;
            bAd0 += 32; bAd1 += 32; bAd2 += 32; bAd3 += 32;
            #pragma unroll
            for (int nt = 0; nt < 8; nt++) {
                MMA(acc[0][nt], a0, bb[nt]);
                MMA(acc[1][nt], a1, bb[nt]);
            }
        }
        __syncthreads();                    // buffer (c&1) reusable at c+2
    }
#undef STAGE

    // ---- epilogue: scale * abs, paired stores ----
    const int qn = lane & 3, rr2 = lane >> 2;
    #pragma unroll
    for (int s = 0; s < 2; s++) {
        #pragma unroll
        for (int h = 0; h < 2; h++) {
            int row = w * 32 + s * 16 + rr2 + h * 8;
            int gl  = mtile * 128 + row;
            if (gl < REG) {
                float* __restrict__ orow =
                    out + ((size_t)(b * REG + gl) * NB + band) * TLEN;
                #pragma unroll
                for (int nt = 0; nt < 8; nt++) {
                    int n = n0 + nt * 8 + qn * 2;
                    if (n < TLEN) {
                        float2 v;
                        v.x = sq * fabsf(acc[s][nt][h * 2 + 0]);
                        v.y = sq * fabsf(acc[s][nt][h * 2 + 1]);
                        *(float2*)(orow + n) = v;
                    }
                }
            }
        }
    }
}

// ---------------------------------------------------------------------------
extern "C" void kernel_launch(void* const* d_in, const int* in_sizes, int n_in,
                              void* d_out, int out_size) {
    (void)in_sizes; (void)n_in; (void)out_size;
    const float* ts  = (const float*)d_in[0];
    const float* tr  = (const float*)d_in[1];
    const float* lsp = (const float*)d_in[2];
    const float* bwp = (const float*)d_in[3];
    float* out   = (float*)d_out;
    float* bands = out + (size_t)BATCH * REG * NB * TLEN;

    cudaFuncSetAttribute(k_gemm, cudaFuncAttributeMaxDynamicSharedMemorySize,
                         SMEM_TOTAL);

    k_conv<<<BATCH * REG, 256>>>(ts);
    k_prep<<<BATCH * NB, DMAX>>>(tr, lsp, bwp, bands);
    k_gemm<<<BATCH * NB * MT * NT, 128, SMEM_TOTAL>>>(out);
}